// round 14
// baseline (speedup 1.0000x reference)
#include <cuda_runtime.h>
#include <cstdint>

#define H 1024
#define SEQ 512
#define VOCAB 50257

// logits kernel: 8 warps/block, 2 rows/warp -> 16 rows/block
#define LROWS 16
#define NLOGB ((VOCAB + LROWS - 1) / LROWS)   // 3142

// output layout: [log_softmax(VOCAB) | h(H) | c(H) | attn_weights(SEQ)]
#define OUT_H  (VOCAB)
#define OUT_C  (VOCAB + H)
#define OUT_AW (VOCAB + 2 * H)

// ---------------- device scratch ----------------
__device__ float g_attn_logits[SEQ];
__device__ float g_attn_applied[H];
__device__ float g_x[H];
__device__ float g_h[H];
__device__ float g_ghh[4 * H];   // h0 @ w_hh.T partials
__device__ float g_pmax[NLOGB];
__device__ float g_psum[NLOGB];

// PDL primitives (no-ops without the launch attribute).
__device__ __forceinline__ void pdl_wait() {
    asm volatile("griddepcontrol.wait;" ::: "memory");
}
__device__ __forceinline__ void pdl_trigger() {
    asm volatile("griddepcontrol.launch_dependents;" ::: "memory");
}
__device__ __forceinline__ void prefetch_l2(const void* p) {
    asm volatile("prefetch.global.L2 [%0];" :: "l"(p));
}

__device__ __forceinline__ float dot4(float4 a, float4 b) {
    return a.x * b.x + a.y * b.y + a.z * b.z + a.w * b.w;
}

// Streaming v4 load via inline PTX: volatile ordering forces batched LDG.128.
__device__ __forceinline__ float4 ldcs4(const float4* p) {
    float4 v;
    asm volatile("ld.global.cs.v4.f32 {%0,%1,%2,%3}, [%4];"
                 : "=f"(v.x), "=f"(v.y), "=f"(v.z), "=f"(v.w) : "l"(p));
    return v;
}

// 1024-float dot: 8 batched LDG.128 per lane, FMAs against smem vector.
__device__ __forceinline__ float row_dot_1024(const float4* __restrict__ w,
                                              const float4* s, int lane) {
    float4 w0 = ldcs4(w + lane);
    float4 w1 = ldcs4(w + lane + 32);
    float4 w2 = ldcs4(w + lane + 64);
    float4 w3 = ldcs4(w + lane + 96);
    float4 w4 = ldcs4(w + lane + 128);
    float4 w5 = ldcs4(w + lane + 160);
    float4 w6 = ldcs4(w + lane + 192);
    float4 w7 = ldcs4(w + lane + 224);
    float acc = dot4(s[lane], w0);
    acc += dot4(s[lane + 32],  w1);
    acc += dot4(s[lane + 64],  w2);
    acc += dot4(s[lane + 96],  w3);
    acc += dot4(s[lane + 128], w4);
    acc += dot4(s[lane + 160], w5);
    acc += dot4(s[lane + 192], w6);
    acc += dot4(s[lane + 224], w7);
    return acc;
}

__device__ __forceinline__ float warp_sum(float v) {
#pragma unroll
    for (int o = 16; o > 0; o >>= 1) v += __shfl_down_sync(0xffffffffu, v, o);
    return v;
}

__device__ __forceinline__ float sigmoidf_(float x) {
    return 1.0f / (1.0f + expf(-x));
}

// ---- 1. FUSED: attn scores (0..127) + w_hh partials (128..639)
//          + comb_W L2-prefetch blocks (640..767, trigger-first) ----
__global__ void __launch_bounds__(256) attn_whh_kernel(
        const int* __restrict__ idx, const float* __restrict__ emb,
        const float* __restrict__ h0, const float* __restrict__ attn_W,
        const float* __restrict__ attn_b, const float* __restrict__ w_hh,
        const float* __restrict__ comb_W) {
    __shared__ float4 sin[512];
    __shared__ float spart[8];
    int t = threadIdx.x, warp = t >> 5, lane = t & 31;
    int b = blockIdx.x;
    if (b >= 640) {
        // prefetch-only CTA: trigger first so dependents never wait on us.
        pdl_trigger();
        // comb_W: 8 MB over 128 blocks -> 64 KB/block, 256 B/thread.
        const char* base = (const char*)comb_W
                         + (size_t)(b - 640) * 65536 + (size_t)t * 256;
#pragma unroll
        for (int k = 0; k < 8; k++) prefetch_l2(base + k * 32);
        return;
    }
    if (b < 128) {
        int row = idx[0];
        sin[t]       = ((const float4*)(emb + (size_t)row * H))[t];
        sin[256 + t] = ((const float4*)h0)[t];
        __syncthreads();
        int r    = b * 4 + (warp >> 1);       // rows 0..511
        int half = warp & 1;
        const float4* w = (const float4*)(attn_W + (size_t)r * (2 * H)) + half * 256;
        float acc = row_dot_1024(w, sin + half * 256, lane);
        acc = warp_sum(acc);
        if (lane == 0) spart[warp] = acc;
        __syncthreads();
        if (t < 4) {
            int rr = b * 4 + t;
            g_attn_logits[rr] = spart[2 * t] + spart[2 * t + 1] + attn_b[rr];
        }
        // block 0 zeroes the attn_applied atomic accumulator (stream order
        // makes this race-free: next kernel is the only consumer/producer).
        if (b == 0) ((float4*)g_attn_applied)[t] = make_float4(0.f, 0.f, 0.f, 0.f);
    } else {
        sin[t] = ((const float4*)h0)[t];      // only first 256 entries used
        __syncthreads();
        int r = (b - 128) * 8 + warp;         // 512 blocks * 8 warps = 4096
        const float4* w = (const float4*)(w_hh + (size_t)r * H);
        float acc = row_dot_1024(w, sin, lane);
        acc = warp_sum(acc);
        if (lane == 0) g_ghh[r] = acc;
    }
    __syncthreads();
    __threadfence();
    pdl_trigger();                            // all writes done for this CTA
}

// ---- 2. fused softmax + attn_applied (blocks 0..63)
//         + w_ih L2-prefetch blocks (64..575, trigger-first) ----
__global__ void __launch_bounds__(256) attn_applied_kernel(
        const float* __restrict__ enc, const float* __restrict__ w_ih,
        float* __restrict__ out) {
    __shared__ float sred[256];
    __shared__ float saw[8];
    int t = threadIdx.x;
    int b = blockIdx.x;
    if (b >= 64) {
        pdl_trigger();
        // w_ih: 16 MB over 512 blocks -> 32 KB/block, 128 B/thread.
        const char* base = (const char*)w_ih
                         + (size_t)(b - 64) * 32768 + (size_t)t * 128;
#pragma unroll
        for (int k = 0; k < 4; k++) prefetch_l2(base + k * 32);
        return;
    }
    int r0 = b * 8;                           // 64 work blocks
    const float4* e4 = (const float4*)enc;
    // prefetch this block's 8 encoder rows while the producer drains
#pragma unroll
    for (int s = 0; s < 8; s++) prefetch_l2(&e4[(size_t)(r0 + s) * 256 + t]);
    pdl_wait();                               // needs g_attn_logits, zeros
    float v0 = g_attn_logits[t];
    float v1 = g_attn_logits[t + 256];
    sred[t] = fmaxf(v0, v1);
    __syncthreads();
    for (int k = 128; k > 0; k >>= 1) {
        if (t < k) sred[t] = fmaxf(sred[t], sred[t + k]);
        __syncthreads();
    }
    float m = sred[0];
    __syncthreads();
    float e0 = expf(v0 - m), e1 = expf(v1 - m);
    sred[t] = e0 + e1;
    __syncthreads();
    for (int k = 128; k > 0; k >>= 1) {
        if (t < k) sred[t] += sred[t + k];
        __syncthreads();
    }
    float inv = 1.0f / sred[0];
    if (b == 0) {                             // one block persists the weights
        out[OUT_AW + t] = e0 * inv;
        out[OUT_AW + t + 256] = e1 * inv;
    }
    if (t < 8) saw[t] = expf(g_attn_logits[r0 + t] - m) * inv;
    __syncthreads();
    float4 acc = make_float4(0.f, 0.f, 0.f, 0.f);
#pragma unroll
    for (int s = 0; s < 8; s++) {
        float w = saw[s];
        float4 v = ldcs4(&e4[(size_t)(r0 + s) * 256 + t]);
        acc.x += w * v.x; acc.y += w * v.y; acc.z += w * v.z; acc.w += w * v.w;
    }
    atomicAdd(&g_attn_applied[4 * t + 0], acc.x);
    atomicAdd(&g_attn_applied[4 * t + 1], acc.y);
    atomicAdd(&g_attn_applied[4 * t + 2], acc.z);
    atomicAdd(&g_attn_applied[4 * t + 3], acc.w);
    __syncthreads();
    __threadfence();
    pdl_trigger();
}

// ---- 3. comb: 2 warps per row (split-K), 256 blocks x 4 rows ----
__global__ void __launch_bounds__(256) comb_kernel(
        const int* __restrict__ idx, const float* __restrict__ emb,
        const float* __restrict__ comb_W, const float* __restrict__ comb_b) {
    __shared__ float4 sin[512];
    __shared__ float spart[8];
    int t = threadIdx.x, warp = t >> 5, lane = t & 31;
    int r    = blockIdx.x * 4 + (warp >> 1);  // grid = 256 -> rows 0..1023
    int half = warp & 1;
    const float4* w = (const float4*)(comb_W + (size_t)r * (2 * H)) + half * 256;
    // prefetch this warp's weight half while the producer drains
#pragma unroll
    for (int k = 0; k < 8; k++) prefetch_l2(w + lane + 32 * k);
    int row = idx[0];
    sin[t] = ((const float4*)(emb + (size_t)row * H))[t];  // input-only, pre-wait
    pdl_wait();                               // needs g_attn_applied
    sin[256 + t] = ((const float4*)g_attn_applied)[t];
    __syncthreads();
    float acc = row_dot_1024(w, sin + half * 256, lane);
    acc = warp_sum(acc);
    if (lane == 0) spart[warp] = acc;
    __syncthreads();
    if (t < 4) {
        int rr = blockIdx.x * 4 + t;
        g_x[rr] = fmaxf(spart[2 * t] + spart[2 * t + 1] + comb_b[rr], 0.0f);
    }
    __syncthreads();
    __threadfence();
    pdl_trigger();
}

// ---- 4. FUSED w_ih GEMV + LSTM: block b owns all 4 gates for j in {2b, 2b+1} ----
__global__ void __launch_bounds__(256) gates_lstm_kernel(
        const float* __restrict__ c0,
        const float* __restrict__ w_ih,
        const float* __restrict__ b_ih, const float* __restrict__ b_hh,
        float* __restrict__ out) {
    __shared__ float4 sx[256];
    __shared__ float sgate[8];                // [g*2 + jj]
    int t = threadIdx.x, warp = t >> 5, lane = t & 31;
    int b = blockIdx.x;                       // grid = 512
    int g = warp >> 1, jj = warp & 1;
    int j = b * 2 + jj;
    size_t r = (size_t)g * H + j;
    const float4* w = (const float4*)(w_ih + r * H);
    // prefetch this warp's full weight row while comb drains
#pragma unroll
    for (int k = 0; k < 8; k++) prefetch_l2(w + lane + 32 * k);
    pdl_wait();                               // needs g_x (and g_ghh from K1)
    sx[t] = ((const float4*)g_x)[t];
    __syncthreads();
    float acc = row_dot_1024(w, sx, lane);
    acc = warp_sum(acc);
    if (lane == 0) sgate[warp] = acc + g_ghh[r] + b_ih[r] + b_hh[r];
    __syncthreads();
    if (t < 2) {
        int jo = b * 2 + t;
        float i_ = sigmoidf_(sgate[0 + t]);
        float f_ = sigmoidf_(sgate[2 + t]);
        float g_ = tanhf(sgate[4 + t]);
        float o_ = sigmoidf_(sgate[6 + t]);
        float c = f_ * c0[jo] + i_ * g_;
        float h = o_ * tanhf(c);
        g_h[jo] = h;
        out[OUT_H + jo] = h;
        out[OUT_C + jo] = c;
    }
    __syncthreads();
    __threadfence();
    pdl_trigger();
}

// ---- 5. logits + fused block LSE: 2 rows per warp, inline loads ----
__global__ void __launch_bounds__(256) logits_kernel(
        const float* __restrict__ out_W, const float* __restrict__ out_b,
        float* __restrict__ out) {
    __shared__ float4 sh[256];
    __shared__ float s_m[8], s_s[8];
    int t = threadIdx.x, warp = t >> 5, lane = t & 31;
    int r0 = blockIdx.x * LROWS + warp * 2;   // grid = NLOGB
    int r1 = r0 + 1;
    const float4* w0 = (const float4*)(out_W + (size_t)r0 * H);
    const float4* w1 = (const float4*)(out_W + (size_t)r1 * H);
    bool has0 = (r0 < VOCAB);
    bool has1 = (r1 < VOCAB);
    if (has0) {
        // prefetch both weight rows while gates drains (input-only addresses)
#pragma unroll
        for (int k = 0; k < 8; k++) {
            prefetch_l2(w0 + lane + 32 * k);
            if (has1) prefetch_l2(w1 + lane + 32 * k);
        }
    }
    pdl_wait();                               // needs g_h
    sh[t] = ((const float4*)g_h)[t];
    __syncthreads();
    float m = -1e30f, s = 0.0f;
    if (has0) {
        float acc0 = 0.0f, acc1 = 0.0f;
#pragma unroll
        for (int k = 0; k < 8; k++) {
            int i = lane + 32 * k;
            float4 hv = sh[i];
            acc0 += dot4(hv, __ldcs(&w0[i]));
            if (has1) acc1 += dot4(hv, __ldcs(&w1[i]));
        }
        acc0 = warp_sum(acc0);
        acc1 = warp_sum(acc1);
        if (lane == 0) {
            float L0 = acc0 + out_b[r0];
            out[r0] = L0;
            m = L0; s = 1.0f;
            if (has1) {
                float L1 = acc1 + out_b[r1];
                out[r1] = L1;
                float M = fmaxf(m, L1);
                s = expf(m - M) + expf(L1 - M);
                m = M;
            }
        }
    }
    if (lane == 0) { s_m[warp] = m; s_s[warp] = s; }
    __syncthreads();
    if (t == 0) {
        float M = s_m[0], S = s_s[0];
#pragma unroll
        for (int k = 1; k < 8; k++) {
            float m2 = s_m[k], s2 = s_s[k];
            float Mx = fmaxf(M, m2);
            S = S * expf(M - Mx) + s2 * expf(m2 - Mx);
            M = Mx;
        }
        g_pmax[blockIdx.x] = M;
        g_psum[blockIdx.x] = S;
    }
    __syncthreads();
    __threadfence();
    pdl_trigger();
}

// ---- 6. final LSE combine (redundant per block) + subtract ----
__global__ void __launch_bounds__(256) sub_lse_kernel(float* __restrict__ out) {
    __shared__ float rm[256], rs[256];
    int t = threadIdx.x;
    pdl_wait();                               // needs g_pmax/g_psum + logits
    float m = -1e30f, s = 0.0f;
    for (int i = t; i < NLOGB; i += 256) {
        float m2 = g_pmax[i], s2 = g_psum[i];
        float M = fmaxf(m, m2);
        s = s * expf(m - M) + s2 * expf(m2 - M);
        m = M;
    }
    rm[t] = m; rs[t] = s;
    __syncthreads();
    for (int k = 128; k > 0; k >>= 1) {
        if (t < k) {
            float m2 = rm[t + k], s2 = rs[t + k];
            float M = fmaxf(rm[t], m2);
            rs[t] = rs[t] * expf(rm[t] - M) + s2 * expf(m2 - M);
            rm[t] = M;
        }
        __syncthreads();
    }
    float lse = rm[0] + logf(rs[0]);
    int base = blockIdx.x * 1024;             // grid = 50
#pragma unroll
    for (int k = 0; k < 4; k++) {
        int i = base + t + 256 * k;
        if (i < VOCAB) out[i] -= lse;
    }
}

// Host-side: launch with the PDL (programmatic stream serialization) attr so
// each kernel's blocks become resident while the predecessor still runs.
template <typename F, typename... Args>
static inline void launch_pdl(F kernel, dim3 grid, dim3 block, Args... args) {
    cudaLaunchConfig_t cfg = {};
    cfg.gridDim = grid;
    cfg.blockDim = block;
    cfg.dynamicSmemBytes = 0;
    cfg.stream = 0;                           // legacy default stream (captured)
    cudaLaunchAttribute attr[1];
    attr[0].id = cudaLaunchAttributeProgrammaticStreamSerialization;
    attr[0].val.programmaticStreamSerializationAllowed = 1;
    cfg.attrs = attr;
    cfg.numAttrs = 1;
    cudaLaunchKernelEx(&cfg, kernel, args...);
}

extern "C" void kernel_launch(void* const* d_in, const int* in_sizes, int n_in,
                              void* d_out, int out_size) {
    const int*   idx     = (const int*)  d_in[0];
    const float* h0      = (const float*)d_in[1];
    const float* c0      = (const float*)d_in[2];
    const float* enc     = (const float*)d_in[3];
    const float* emb     = (const float*)d_in[4];
    const float* attn_W  = (const float*)d_in[5];
    const float* attn_b  = (const float*)d_in[6];
    const float* comb_W  = (const float*)d_in[7];
    const float* comb_b  = (const float*)d_in[8];
    const float* w_ih    = (const float*)d_in[9];
    const float* w_hh    = (const float*)d_in[10];
    const float* b_ih    = (const float*)d_in[11];
    const float* b_hh    = (const float*)d_in[12];
    const float* out_W   = (const float*)d_in[13];
    const float* out_b   = (const float*)d_in[14];
    float* out = (float*)d_out;

    attn_whh_kernel<<<768, 256>>>(idx, emb, h0, attn_W, attn_b, w_hh, comb_W);
    launch_pdl(attn_applied_kernel, dim3(576), dim3(256), enc, w_ih, out);
    launch_pdl(comb_kernel, dim3(H / 4), dim3(256), idx, emb, comb_W, comb_b);
    launch_pdl(gates_lstm_kernel, dim3(512), dim3(256), c0, w_ih, b_ih, b_hh, out);
    launch_pdl(logits_kernel, dim3(NLOGB), dim3(256), out_W, out_b, out);
    launch_pdl(sub_lse_kernel, dim3((VOCAB + 1023) / 1024), dim3(256), out);
}

// round 15
// speedup vs baseline: 1.0842x; 1.0842x over previous
#include <cuda_runtime.h>
#include <cstdint>

#define H 1024
#define SEQ 512
#define VOCAB 50257

// logits kernel: 8 warps/block, 2 rows/warp -> 16 rows/block
#define LROWS 16
#define NLOGB ((VOCAB + LROWS - 1) / LROWS)   // 3142

// output layout: [log_softmax(VOCAB) | h(H) | c(H) | attn_weights(SEQ)]
#define OUT_H  (VOCAB)
#define OUT_C  (VOCAB + H)
#define OUT_AW (VOCAB + 2 * H)

// ---------------- device scratch ----------------
__device__ float g_attn_logits[SEQ];
__device__ float g_attn_applied[H];
__device__ float g_x[H];
__device__ float g_h[H];
__device__ float g_ghh[4 * H];   // h0 @ w_hh.T partials
__device__ float g_pmax[NLOGB];
__device__ float g_psum[NLOGB];

// PDL primitives (no-ops without the launch attribute).
__device__ __forceinline__ void pdl_wait() {
    asm volatile("griddepcontrol.wait;" ::: "memory");
}
__device__ __forceinline__ void pdl_trigger() {
    asm volatile("griddepcontrol.launch_dependents;" ::: "memory");
}
__device__ __forceinline__ void prefetch_l2(const void* p) {
    asm volatile("prefetch.global.L2 [%0];" :: "l"(p));
}

__device__ __forceinline__ float dot4(float4 a, float4 b) {
    return a.x * b.x + a.y * b.y + a.z * b.z + a.w * b.w;
}

// Streaming v4 load via inline PTX: volatile ordering forces batched LDG.128.
__device__ __forceinline__ float4 ldcs4(const float4* p) {
    float4 v;
    asm volatile("ld.global.cs.v4.f32 {%0,%1,%2,%3}, [%4];"
                 : "=f"(v.x), "=f"(v.y), "=f"(v.z), "=f"(v.w) : "l"(p));
    return v;
}

// 1024-float dot: 8 batched LDG.128 per lane, FMAs against smem vector.
__device__ __forceinline__ float row_dot_1024(const float4* __restrict__ w,
                                              const float4* s, int lane) {
    float4 w0 = ldcs4(w + lane);
    float4 w1 = ldcs4(w + lane + 32);
    float4 w2 = ldcs4(w + lane + 64);
    float4 w3 = ldcs4(w + lane + 96);
    float4 w4 = ldcs4(w + lane + 128);
    float4 w5 = ldcs4(w + lane + 160);
    float4 w6 = ldcs4(w + lane + 192);
    float4 w7 = ldcs4(w + lane + 224);
    float acc = dot4(s[lane], w0);
    acc += dot4(s[lane + 32],  w1);
    acc += dot4(s[lane + 64],  w2);
    acc += dot4(s[lane + 96],  w3);
    acc += dot4(s[lane + 128], w4);
    acc += dot4(s[lane + 160], w5);
    acc += dot4(s[lane + 192], w6);
    acc += dot4(s[lane + 224], w7);
    return acc;
}

__device__ __forceinline__ float warp_sum(float v) {
#pragma unroll
    for (int o = 16; o > 0; o >>= 1) v += __shfl_down_sync(0xffffffffu, v, o);
    return v;
}

__device__ __forceinline__ float sigmoidf_(float x) {
    return 1.0f / (1.0f + expf(-x));
}

// ---- 1. attention scores only (128 blocks): short critical-path producer ----
__global__ void __launch_bounds__(256) attn_score_kernel(
        const int* __restrict__ idx, const float* __restrict__ emb,
        const float* __restrict__ h0, const float* __restrict__ attn_W,
        const float* __restrict__ attn_b) {
    __shared__ float4 sin[512];
    __shared__ float spart[8];
    int t = threadIdx.x, warp = t >> 5, lane = t & 31;
    int b = blockIdx.x;
    int row = idx[0];
    sin[t]       = ((const float4*)(emb + (size_t)row * H))[t];
    sin[256 + t] = ((const float4*)h0)[t];
    __syncthreads();
    int r    = b * 4 + (warp >> 1);           // rows 0..511
    int half = warp & 1;
    const float4* w = (const float4*)(attn_W + (size_t)r * (2 * H)) + half * 256;
    float acc = row_dot_1024(w, sin + half * 256, lane);
    acc = warp_sum(acc);
    if (lane == 0) spart[warp] = acc;
    __syncthreads();
    if (t < 4) {
        int rr = b * 4 + t;
        g_attn_logits[rr] = spart[2 * t] + spart[2 * t + 1] + attn_b[rr];
    }
    // block 0 zeroes the attn_applied atomic accumulator (stream order makes
    // this race-free: next kernel is the only consumer/producer).
    if (b == 0) ((float4*)g_attn_applied)[t] = make_float4(0.f, 0.f, 0.f, 0.f);
    __syncthreads();
    __threadfence();
    pdl_trigger();                            // all writes done for this CTA
}

// ---- 2. fused softmax (redundant per block) + attn_applied slice ----
__global__ void __launch_bounds__(256) attn_applied_kernel(
        const float* __restrict__ enc, float* __restrict__ out) {
    __shared__ float sred[256];
    __shared__ float saw[8];
    int t = threadIdx.x;
    int r0 = blockIdx.x * 8;                  // grid = 64
    const float4* e4 = (const float4*)enc;
    // prefetch this block's 8 encoder rows while the producer drains
#pragma unroll
    for (int s = 0; s < 8; s++) prefetch_l2(&e4[(size_t)(r0 + s) * 256 + t]);
    pdl_wait();                               // needs g_attn_logits, zeros
    float v0 = g_attn_logits[t];
    float v1 = g_attn_logits[t + 256];
    sred[t] = fmaxf(v0, v1);
    __syncthreads();
    for (int k = 128; k > 0; k >>= 1) {
        if (t < k) sred[t] = fmaxf(sred[t], sred[t + k]);
        __syncthreads();
    }
    float m = sred[0];
    __syncthreads();
    float e0 = expf(v0 - m), e1 = expf(v1 - m);
    sred[t] = e0 + e1;
    __syncthreads();
    for (int k = 128; k > 0; k >>= 1) {
        if (t < k) sred[t] += sred[t + k];
        __syncthreads();
    }
    float inv = 1.0f / sred[0];
    if (blockIdx.x == 0) {                    // one block persists the weights
        out[OUT_AW + t] = e0 * inv;
        out[OUT_AW + t + 256] = e1 * inv;
    }
    if (t < 8) saw[t] = expf(g_attn_logits[r0 + t] - m) * inv;
    __syncthreads();
    float4 acc = make_float4(0.f, 0.f, 0.f, 0.f);
#pragma unroll
    for (int s = 0; s < 8; s++) {
        float w = saw[s];
        float4 v = ldcs4(&e4[(size_t)(r0 + s) * 256 + t]);
        acc.x += w * v.x; acc.y += w * v.y; acc.z += w * v.z; acc.w += w * v.w;
    }
    atomicAdd(&g_attn_applied[4 * t + 0], acc.x);
    atomicAdd(&g_attn_applied[4 * t + 1], acc.y);
    atomicAdd(&g_attn_applied[4 * t + 2], acc.z);
    atomicAdd(&g_attn_applied[4 * t + 3], acc.w);
    __syncthreads();
    __threadfence();
    pdl_trigger();
}

// ---- 3. FUSED: comb (blocks 0..255, waits) + w_hh partials (256..767, no wait) ----
// w_hh depends only on the kernel input h0, so those CTAs skip pdl_wait and run
// concurrently with comb. Their trigger-at-end transitively orders g_ghh
// before K4's pdl_wait.
__global__ void __launch_bounds__(256) comb_whh_kernel(
        const int* __restrict__ idx, const float* __restrict__ emb,
        const float* __restrict__ comb_W, const float* __restrict__ comb_b,
        const float* __restrict__ h0, const float* __restrict__ w_hh) {
    __shared__ float4 sin[512];
    __shared__ float spart[8];
    int t = threadIdx.x, warp = t >> 5, lane = t & 31;
    int b = blockIdx.x;
    if (b >= 256) {
        // ----- w_hh partials: warp per row, rows 0..4095, no dependency -----
        sin[t] = ((const float4*)h0)[t];      // only first 256 entries used
        __syncthreads();
        int r = (b - 256) * 8 + warp;         // 512 blocks * 8 warps = 4096
        const float4* w = (const float4*)(w_hh + (size_t)r * H);
        float acc = row_dot_1024(w, sin, lane);
        acc = warp_sum(acc);
        if (lane == 0) g_ghh[r] = acc;
        __syncthreads();
        __threadfence();
        pdl_trigger();
        return;
    }
    // ----- comb: 2 warps per row (split-K), 4 rows/block -----
    int r    = b * 4 + (warp >> 1);           // rows 0..1023
    int half = warp & 1;
    const float4* w = (const float4*)(comb_W + (size_t)r * (2 * H)) + half * 256;
    // prefetch this warp's weight half while the producer drains
#pragma unroll
    for (int k = 0; k < 8; k++) prefetch_l2(w + lane + 32 * k);
    int row = idx[0];
    sin[t] = ((const float4*)(emb + (size_t)row * H))[t];  // input-only, pre-wait
    pdl_wait();                               // needs g_attn_applied
    sin[256 + t] = ((const float4*)g_attn_applied)[t];
    __syncthreads();
    float acc = row_dot_1024(w, sin + half * 256, lane);
    acc = warp_sum(acc);
    if (lane == 0) spart[warp] = acc;
    __syncthreads();
    if (t < 4) {
        int rr = b * 4 + t;
        g_x[rr] = fmaxf(spart[2 * t] + spart[2 * t + 1] + comb_b[rr], 0.0f);
    }
    __syncthreads();
    __threadfence();
    pdl_trigger();
}

// ---- 4. FUSED w_ih GEMV + LSTM: block b owns all 4 gates for j in {2b, 2b+1} ----
__global__ void __launch_bounds__(256) gates_lstm_kernel(
        const float* __restrict__ c0,
        const float* __restrict__ w_ih,
        const float* __restrict__ b_ih, const float* __restrict__ b_hh,
        float* __restrict__ out) {
    __shared__ float4 sx[256];
    __shared__ float sgate[8];                // [g*2 + jj]
    int t = threadIdx.x, warp = t >> 5, lane = t & 31;
    int b = blockIdx.x;                       // grid = 512
    int g = warp >> 1, jj = warp & 1;
    int j = b * 2 + jj;
    size_t r = (size_t)g * H + j;
    const float4* w = (const float4*)(w_ih + r * H);
    // prefetch this warp's full weight row while comb/whh drain
#pragma unroll
    for (int k = 0; k < 8; k++) prefetch_l2(w + lane + 32 * k);
    pdl_wait();                               // needs g_x and g_ghh (via K3)
    sx[t] = ((const float4*)g_x)[t];
    __syncthreads();
    float acc = row_dot_1024(w, sx, lane);
    acc = warp_sum(acc);
    if (lane == 0) sgate[warp] = acc + g_ghh[r] + b_ih[r] + b_hh[r];
    __syncthreads();
    if (t < 2) {
        int jo = b * 2 + t;
        float i_ = sigmoidf_(sgate[0 + t]);
        float f_ = sigmoidf_(sgate[2 + t]);
        float g_ = tanhf(sgate[4 + t]);
        float o_ = sigmoidf_(sgate[6 + t]);
        float c = f_ * c0[jo] + i_ * g_;
        float h = o_ * tanhf(c);
        g_h[jo] = h;
        out[OUT_H + jo] = h;
        out[OUT_C + jo] = c;
    }
    __syncthreads();
    __threadfence();
    pdl_trigger();
}

// ---- 5. logits + fused block LSE: 2 rows per warp, inline loads ----
__global__ void __launch_bounds__(256) logits_kernel(
        const float* __restrict__ out_W, const float* __restrict__ out_b,
        float* __restrict__ out) {
    __shared__ float4 sh[256];
    __shared__ float s_m[8], s_s[8];
    int t = threadIdx.x, warp = t >> 5, lane = t & 31;
    int r0 = blockIdx.x * LROWS + warp * 2;   // grid = NLOGB
    int r1 = r0 + 1;
    const float4* w0 = (const float4*)(out_W + (size_t)r0 * H);
    const float4* w1 = (const float4*)(out_W + (size_t)r1 * H);
    bool has0 = (r0 < VOCAB);
    bool has1 = (r1 < VOCAB);
    if (has0) {
        // prefetch both weight rows while gates drains (input-only addresses)
#pragma unroll
        for (int k = 0; k < 8; k++) {
            prefetch_l2(w0 + lane + 32 * k);
            if (has1) prefetch_l2(w1 + lane + 32 * k);
        }
    }
    pdl_wait();                               // needs g_h
    sh[t] = ((const float4*)g_h)[t];
    __syncthreads();
    float m = -1e30f, s = 0.0f;
    if (has0) {
        float acc0 = 0.0f, acc1 = 0.0f;
#pragma unroll
        for (int k = 0; k < 8; k++) {
            int i = lane + 32 * k;
            float4 hv = sh[i];
            acc0 += dot4(hv, __ldcs(&w0[i]));
            if (has1) acc1 += dot4(hv, __ldcs(&w1[i]));
        }
        acc0 = warp_sum(acc0);
        acc1 = warp_sum(acc1);
        if (lane == 0) {
            float L0 = acc0 + out_b[r0];
            out[r0] = L0;
            m = L0; s = 1.0f;
            if (has1) {
                float L1 = acc1 + out_b[r1];
                out[r1] = L1;
                float M = fmaxf(m, L1);
                s = expf(m - M) + expf(L1 - M);
                m = M;
            }
        }
    }
    if (lane == 0) { s_m[warp] = m; s_s[warp] = s; }
    __syncthreads();
    if (t == 0) {
        float M = s_m[0], S = s_s[0];
#pragma unroll
        for (int k = 1; k < 8; k++) {
            float m2 = s_m[k], s2 = s_s[k];
            float Mx = fmaxf(M, m2);
            S = S * expf(M - Mx) + s2 * expf(m2 - Mx);
            M = Mx;
        }
        g_pmax[blockIdx.x] = M;
        g_psum[blockIdx.x] = S;
    }
    __syncthreads();
    __threadfence();
    pdl_trigger();
}

// ---- 6. final LSE combine (redundant per block) + subtract ----
__global__ void __launch_bounds__(256) sub_lse_kernel(float* __restrict__ out) {
    __shared__ float rm[256], rs[256];
    int t = threadIdx.x;
    pdl_wait();                               // needs g_pmax/g_psum + logits
    float m = -1e30f, s = 0.0f;
    for (int i = t; i < NLOGB; i += 256) {
        float m2 = g_pmax[i], s2 = g_psum[i];
        float M = fmaxf(m, m2);
        s = s * expf(m - M) + s2 * expf(m2 - M);
        m = M;
    }
    rm[t] = m; rs[t] = s;
    __syncthreads();
    for (int k = 128; k > 0; k >>= 1) {
        if (t < k) {
            float m2 = rm[t + k], s2 = rs[t + k];
            float M = fmaxf(rm[t], m2);
            rs[t] = rs[t] * expf(rm[t] - M) + s2 * expf(m2 - M);
            rm[t] = M;
        }
        __syncthreads();
    }
    float lse = rm[0] + logf(rs[0]);
    int base = blockIdx.x * 1024;             // grid = 50
#pragma unroll
    for (int k = 0; k < 4; k++) {
        int i = base + t + 256 * k;
        if (i < VOCAB) out[i] -= lse;
    }
}

// Host-side: launch with the PDL (programmatic stream serialization) attr so
// each kernel's blocks become resident while the predecessor still runs.
template <typename F, typename... Args>
static inline void launch_pdl(F kernel, dim3 grid, dim3 block, Args... args) {
    cudaLaunchConfig_t cfg = {};
    cfg.gridDim = grid;
    cfg.blockDim = block;
    cfg.dynamicSmemBytes = 0;
    cfg.stream = 0;                           // legacy default stream (captured)
    cudaLaunchAttribute attr[1];
    attr[0].id = cudaLaunchAttributeProgrammaticStreamSerialization;
    attr[0].val.programmaticStreamSerializationAllowed = 1;
    cfg.attrs = attr;
    cfg.numAttrs = 1;
    cudaLaunchKernelEx(&cfg, kernel, args...);
}

extern "C" void kernel_launch(void* const* d_in, const int* in_sizes, int n_in,
                              void* d_out, int out_size) {
    const int*   idx     = (const int*)  d_in[0];
    const float* h0      = (const float*)d_in[1];
    const float* c0      = (const float*)d_in[2];
    const float* enc     = (const float*)d_in[3];
    const float* emb     = (const float*)d_in[4];
    const float* attn_W  = (const float*)d_in[5];
    const float* attn_b  = (const float*)d_in[6];
    const float* comb_W  = (const float*)d_in[7];
    const float* comb_b  = (const float*)d_in[8];
    const float* w_ih    = (const float*)d_in[9];
    const float* w_hh    = (const float*)d_in[10];
    const float* b_ih    = (const float*)d_in[11];
    const float* b_hh    = (const float*)d_in[12];
    const float* out_W   = (const float*)d_in[13];
    const float* out_b   = (const float*)d_in[14];
    float* out = (float*)d_out;

    attn_score_kernel<<<128, 256>>>(idx, emb, h0, attn_W, attn_b);
    launch_pdl(attn_applied_kernel, dim3(64), dim3(256), enc, out);
    launch_pdl(comb_whh_kernel, dim3(768), dim3(256), idx, emb, comb_W, comb_b, h0, w_hh);
    launch_pdl(gates_lstm_kernel, dim3(512), dim3(256), c0, w_ih, b_ih, b_hh, out);
    launch_pdl(logits_kernel, dim3(NLOGB), dim3(256), out_W, out_b, out);
    launch_pdl(sub_lse_kernel, dim3((VOCAB + 1023) / 1024), dim3(256), out);
}